// round 16
// baseline (speedup 1.0000x reference)
#include <cuda_runtime.h>
#include <cstdint>

// R15 resubmission (R15 bench died to infra: "container failed twice" on a
// pure-SIMT kernel with no hangable constructs; theory unfalsified).
// Scores are bit-identical to the R7 passing kernel (rel_err 9.569133e-07).

// Problem constants (fixed by reference)
#define M_CAND    50000
#define K_DIM     2304
#define N_HID     1000
#define NUM_WORDS 5000
#define NTOP      2000
#define MAXW      10
#define SORT_N    65536
#define NTILES    8        // ceil(N_HID/128)

// GEMM tiling: 128x128 tile, k-chunk 16, double-buffered
#define KC        16
#define NCHUNK    (K_DIM / KC)              // 144
#define NMTILE    ((M_CAND + 127) / 128)    // 391
#define A_BUF_F   (KC * 256)                // duplicated A: 16 k x 256 (2x128 rows)
#define B_BUF_F   (KC * 128)
#define SMEM_BYTES ((2 * (A_BUF_F + B_BUF_F)) * 4)   // 49152

// -------- scratch (device globals; no allocation allowed) --------
__device__ float               g_partial[(size_t)M_CAND * NTILES];
__device__ float               g_scores[M_CAND];
__device__ unsigned long long  g_keys[SORT_N];
__device__ int                 g_sel[NTOP];

// ---- packed f32x2 helpers (IEEE-exact: lanes are independent fp32 FMAs) ----
__device__ __forceinline__ void upk2(unsigned long long v, float& x, float& y) {
    asm("mov.b64 {%0, %1}, %2;" : "=f"(x), "=f"(y) : "l"(v));
}
__device__ __forceinline__ unsigned long long ffma2(unsigned long long a,
                                                    unsigned long long b,
                                                    unsigned long long c) {
    unsigned long long d;
    asm("fma.rn.f32x2 %0, %1, %2, %3;" : "=l"(d) : "l"(a), "l"(b), "l"(c));
    return d;
}

// ============================================================
// 1) Fused GEMM: h = relu(A@W1 + b1); partial = h_tile . W2_tile
//    Bit-identical arithmetic to the R7 passing kernel:
//      - per (row,col): fp32 FMA chain, k ascending 0..2303
//      - epilogue: j 0..7 ascending per thread, tn 0..15 ascending, tiles ascending
//    Perf: duplicated-A smem (no splat MOVs) + double-buffered prefetch (1 bar/chunk)
// ============================================================
__global__ void __launch_bounds__(256, 2)
gemm_fused_kernel(const float* __restrict__ A,
                  const float* __restrict__ B,
                  const float* __restrict__ b1,
                  const float* __restrict__ W2) {
    extern __shared__ float sm[];
    float* AdupBase = sm;                       // [2][KC][256]
    float* BsBase   = sm + 2 * A_BUF_F;         // [2][KC][128]

    const int bm = blockIdx.y * 128;
    const int bn = blockIdx.x * 128;
    const int tid = threadIdx.x;
    const int tm = tid >> 4, tn = tid & 15;

    // A loader: two float4 per chunk: rows ar0, ar0+64, cols ac..ac+3
    const int ar0 = tid >> 2;
    const int ac  = (tid & 3) << 2;
    // B loader: two float4 per chunk: k rows kk0, kk0+8, cols bc..bc+3
    const int kk0 = tid >> 5;
    const int bc  = (tid & 31) << 2;
    const int gc  = bn + bc;

    unsigned long long acc2[8][4];
#pragma unroll
    for (int i = 0; i < 8; i++)
#pragma unroll
        for (int jp = 0; jp < 4; jp++) acc2[i][jp] = 0ull;

    float4 avA0, avA1, avB0, avB1;

    // ---- prefetch helpers ----
    auto load_chunk = [&](int c) {
        const int k0 = c * KC;
        avA0 = make_float4(0.f, 0.f, 0.f, 0.f);
        avA1 = make_float4(0.f, 0.f, 0.f, 0.f);
        int gr0 = bm + ar0, gr1 = bm + ar0 + 64;
        if (gr0 < M_CAND)
            avA0 = *reinterpret_cast<const float4*>(&A[(size_t)gr0 * K_DIM + k0 + ac]);
        if (gr1 < M_CAND)
            avA1 = *reinterpret_cast<const float4*>(&A[(size_t)gr1 * K_DIM + k0 + ac]);
        const float* brp0 = &B[(size_t)(k0 + kk0) * N_HID];
        const float* brp1 = &B[(size_t)(k0 + kk0 + 8) * N_HID];
        avB0 = make_float4(0.f, 0.f, 0.f, 0.f);
        avB1 = make_float4(0.f, 0.f, 0.f, 0.f);
        if (gc + 3 < N_HID) {
            avB0 = *reinterpret_cast<const float4*>(&brp0[gc]);
            avB1 = *reinterpret_cast<const float4*>(&brp1[gc]);
        } else {
            if (gc + 0 < N_HID) { avB0.x = brp0[gc + 0]; avB1.x = brp1[gc + 0]; }
            if (gc + 1 < N_HID) { avB0.y = brp0[gc + 1]; avB1.y = brp1[gc + 1]; }
            if (gc + 2 < N_HID) { avB0.z = brp0[gc + 2]; avB1.z = brp1[gc + 2]; }
        }
    };
    auto store_chunk = [&](int buf) {
        float* Ad = AdupBase + buf * A_BUF_F;
        float* Bs = BsBase + buf * B_BUF_F;
        // duplicated A: Ad[k][2r] = Ad[k][2r+1] = a(r,k)
        const float va0[4] = {avA0.x, avA0.y, avA0.z, avA0.w};
        const float va1[4] = {avA1.x, avA1.y, avA1.z, avA1.w};
#pragma unroll
        for (int j = 0; j < 4; j++) {
            *reinterpret_cast<float2*>(&Ad[(ac + j) * 256 + 2 * ar0]) =
                make_float2(va0[j], va0[j]);
            *reinterpret_cast<float2*>(&Ad[(ac + j) * 256 + 2 * (ar0 + 64)]) =
                make_float2(va1[j], va1[j]);
        }
        *reinterpret_cast<float4*>(&Bs[kk0 * 128 + bc]) = avB0;
        *reinterpret_cast<float4*>(&Bs[(kk0 + 8) * 128 + bc]) = avB1;
    };

    load_chunk(0);
    store_chunk(0);
    __syncthreads();

    for (int c = 0; c < NCHUNK; c++) {
        const int buf = c & 1;
        if (c + 1 < NCHUNK) load_chunk(c + 1);

        const float* Ad = AdupBase + buf * A_BUF_F;
        const float* Bs = BsBase + buf * B_BUF_F;
#pragma unroll
        for (int k = 0; k < KC; k++) {
            // 8 A-splat pairs straight from duplicated smem (no MOVs)
            const ulonglong2* ap =
                reinterpret_cast<const ulonglong2*>(&Ad[k * 256 + tm * 16]);
            ulonglong2 a01 = ap[0], a23 = ap[1], a45 = ap[2], a67 = ap[3];
            unsigned long long aspl[8] = {a01.x, a01.y, a23.x, a23.y,
                                          a45.x, a45.y, a67.x, a67.y};
            const ulonglong2* bp =
                reinterpret_cast<const ulonglong2*>(&Bs[k * 128 + tn * 8]);
            ulonglong2 bA = bp[0], bB = bp[1];
            unsigned long long rb2[4] = {bA.x, bA.y, bB.x, bB.y};
#pragma unroll
            for (int i = 0; i < 8; i++)
#pragma unroll
                for (int jp = 0; jp < 4; jp++)
                    acc2[i][jp] = ffma2(aspl[i], rb2[jp], acc2[i][jp]);
        }
        if (c + 1 < NCHUNK) store_chunk((c + 1) & 1);
        __syncthreads();
    }

    // Fused epilogue: relu(acc + b1) dot W2 per row — identical order to R7
    float rowsum[8];
#pragma unroll
    for (int i = 0; i < 8; i++) rowsum[i] = 0.f;
#pragma unroll
    for (int jp = 0; jp < 4; jp++) {
#pragma unroll
        for (int h = 0; h < 2; h++) {
            int j = 2 * jp + h;
            int col = bn + tn * 8 + j;
            if (col < N_HID) {
                float w = W2[col];
                float bb = b1[col];
#pragma unroll
                for (int i = 0; i < 8; i++) {
                    float v0, v1;
                    upk2(acc2[i][jp], v0, v1);
                    float v = (h == 0 ? v0 : v1) + bb;
                    v = v > 0.f ? v : 0.f;
                    rowsum[i] = fmaf(v, w, rowsum[i]);
                }
            }
        }
    }
    // reuse smem as sred[128][17] (all compute done; final bar above)
    float* sred = sm;
#pragma unroll
    for (int i = 0; i < 8; i++) sred[(tm * 8 + i) * 17 + tn] = rowsum[i];
    __syncthreads();

    if (tid < 128) {
        float s = 0.f;
#pragma unroll
        for (int t = 0; t < 16; t++) s += sred[tid * 17 + t];   // tn ascending
        int r = bm + tid;
        if (r < M_CAND) g_partial[(size_t)r * NTILES + blockIdx.x] = s;
    }
}

// ============================================================
// 2) scores[i] = sum_t partial[i][t] + b2  (fixed order)
// ============================================================
__global__ void reduce_scores_kernel(const float* __restrict__ b2) {
    int i = blockIdx.x * blockDim.x + threadIdx.x;
    if (i < M_CAND) {
        float s = 0.f;
#pragma unroll
        for (int t = 0; t < NTILES; t++) s += g_partial[(size_t)i * NTILES + t];
        g_scores[i] = s + b2[0];
    }
}

// ============================================================
// 3) sort keys: (descending score bits << 32) | idx -> ascending u64 sort
// ============================================================
__global__ void build_keys_kernel() {
    int i = blockIdx.x * blockDim.x + threadIdx.x;
    if (i >= SORT_N) return;
    if (i < M_CAND) {
        unsigned u = __float_as_uint(g_scores[i]);
        unsigned m = (u & 0x80000000u) ? ~u : (u | 0x80000000u);
        unsigned d = ~m;
        g_keys[i] = (((unsigned long long)d) << 32) | (unsigned)i;
    } else {
        g_keys[i] = ~0ull;
    }
}

__device__ __forceinline__ void cmpswap(unsigned long long& a, unsigned long long& b, bool up) {
    if ((a > b) == up) { unsigned long long t = a; a = b; b = t; }
}

__global__ void bitonic_local_sort() {
    __shared__ unsigned long long s[4096];
    const int base = blockIdx.x * 4096;
    for (int i = threadIdx.x; i < 4096; i += blockDim.x) s[i] = g_keys[base + i];
    __syncthreads();
    for (int k = 2; k <= 4096; k <<= 1) {
        for (int j = k >> 1; j > 0; j >>= 1) {
            for (int i = threadIdx.x; i < 4096; i += blockDim.x) {
                int l = i ^ j;
                if (l > i) {
                    bool up = (((base + i) & k) == 0);
                    unsigned long long a = s[i], b = s[l];
                    cmpswap(a, b, up);
                    s[i] = a; s[l] = b;
                }
            }
            __syncthreads();
        }
    }
    for (int i = threadIdx.x; i < 4096; i += blockDim.x) g_keys[base + i] = s[i];
}

__global__ void bitonic_global_step(int k, int j) {
    int i = blockIdx.x * blockDim.x + threadIdx.x;
    if (i >= SORT_N) return;
    int l = i ^ j;
    if (l > i) {
        unsigned long long a = g_keys[i], b = g_keys[l];
        bool up = ((i & k) == 0);
        if ((a > b) == up) { g_keys[i] = b; g_keys[l] = a; }
    }
}

__global__ void bitonic_local_merge(int k) {
    __shared__ unsigned long long s[4096];
    const int base = blockIdx.x * 4096;
    for (int i = threadIdx.x; i < 4096; i += blockDim.x) s[i] = g_keys[base + i];
    __syncthreads();
    for (int j = 2048; j > 0; j >>= 1) {
        for (int i = threadIdx.x; i < 4096; i += blockDim.x) {
            int l = i ^ j;
            if (l > i) {
                bool up = (((base + i) & k) == 0);
                unsigned long long a = s[i], b = s[l];
                cmpswap(a, b, up);
                s[i] = a; s[l] = b;
            }
        }
        __syncthreads();
    }
    for (int i = threadIdx.x; i < 4096; i += blockDim.x) g_keys[base + i] = s[i];
}

// ============================================================
// 4) greedy extraction: batched shared prefetch + warp-serial scan
// ============================================================
#define XB 1024

__global__ void extract_kernel(const int* __restrict__ starts,
                               const int* __restrict__ ends,
                               const int* __restrict__ ntop_ptr) {
    __shared__ short stme[NUM_WORDS];
    __shared__ short etms[NUM_WORDS];
    __shared__ unsigned long long acc[2048];
    __shared__ int   sh_count;
    __shared__ int   sh_done;
    __shared__ int   bc[XB];
    __shared__ short bs[XB], be[XB];
    const int tid = threadIdx.x;

    for (int i = tid; i < NUM_WORDS; i += blockDim.x) { stme[i] = -1; etms[i] = -1; }
    for (int i = tid; i < 2048; i += blockDim.x) acc[i] = ~0ull;
    if (tid == 0) sh_done = 0;
    __syncthreads();

    int ntop = NTOP;
    if (ntop_ptr) { int v = *ntop_ptr; ntop = v < NTOP ? v : NTOP; }
    int count = 0;

    for (int base = 0; base < M_CAND; base += XB) {
        if (sh_done) break;
        int i = base + tid;
        if (i < M_CAND) {
            unsigned long long kv = g_keys[i];
            int cand = (int)(unsigned)(kv & 0xFFFFFFFFull);
            bc[tid] = cand;
            bs[tid] = (short)starts[cand];
            be[tid] = (short)ends[cand];
        }
        __syncthreads();

        if (tid < 32) {
            const int lane = tid;
            int n = M_CAND - base; if (n > XB) n = XB;
            for (int t = 0; t < n && count < ntop; t++) {
                int s = (int)bs[t], e = (int)be[t];
                bool c = false;
                if (lane <= MAXW) {
                    int pos = s + lane;
                    if (pos <= e) {
                        int me = (int)stme[pos];
                        int ms = (int)etms[pos];
                        c = ((pos > s) && (me > e)) || ((pos < e) && (ms >= 0) && (ms < s));
                    }
                }
                unsigned b = __ballot_sync(0xffffffffu, c);
                if (b == 0u) {
                    if (lane == 0) {
                        if (e > (int)stme[s]) stme[s] = (short)e;
                        int tt = (int)etms[e];
                        if (tt == -1 || s < tt) etms[e] = (short)s;
                        acc[count] = (((unsigned long long)(s * NUM_WORDS + e)) << 27)
                                   | (((unsigned long long)count) << 16)
                                   | (unsigned long long)(unsigned)bc[t];
                    }
                    count++;
                }
                __syncwarp();
            }
            if (lane == 0 && count >= ntop) sh_done = 1;
        }
        __syncthreads();
    }

    if (tid == 0) sh_count = count;
    __syncthreads();

    for (int k = 2; k <= 2048; k <<= 1) {
        for (int j = k >> 1; j > 0; j >>= 1) {
            for (int i = tid; i < 2048; i += blockDim.x) {
                int l = i ^ j;
                if (l > i) {
                    bool up = ((i & k) == 0);
                    unsigned long long a = acc[i], b = acc[l];
                    cmpswap(a, b, up);
                    acc[i] = a; acc[l] = b;
                }
            }
            __syncthreads();
        }
    }
    const int cnt = sh_count;
    for (int i = tid; i < NTOP; i += blockDim.x) {
        unsigned long long v = (i < cnt) ? acc[i] : acc[0];
        g_sel[i] = (int)(v & 0xFFFFull);
    }
}

// ============================================================
// 5) gather outputs: [idx(float) | scores | emb rows]
// ============================================================
__global__ void gather_kernel(const float* __restrict__ emb, float* __restrict__ out,
                              int full_layout) {
    const int b = blockIdx.x;
    const int sel = g_sel[b];
    float* oemb = out + (full_layout ? 2 * NTOP : 0);
    if (full_layout && threadIdx.x == 0) {
        out[b]        = (float)sel;
        out[NTOP + b] = g_scores[sel];
    }
    const float4* src = reinterpret_cast<const float4*>(&emb[(size_t)sel * K_DIM]);
    float4* dst       = reinterpret_cast<float4*>(&oemb[(size_t)b * K_DIM]);
    for (int j = threadIdx.x; j < K_DIM / 4; j += blockDim.x) dst[j] = src[j];
}

// ============================================================
extern "C" void kernel_launch(void* const* d_in, const int* in_sizes, int n_in,
                              void* d_out, int out_size) {
    const float* span_emb = (const float*)d_in[0];
    const float* W1       = (const float*)d_in[1];
    const float* b1       = (const float*)d_in[2];
    const float* W2       = (const float*)d_in[3];
    const float* b2       = (const float*)d_in[4];
    const int*   starts   = (const int*)d_in[5];
    const int*   ends     = (const int*)d_in[6];
    const int*   ntop     = (n_in > 7) ? (const int*)d_in[7] : nullptr;

    cudaFuncSetAttribute(gemm_fused_kernel,
                         cudaFuncAttributeMaxDynamicSharedMemorySize, SMEM_BYTES);

    // 1) fused GEMM + bias + relu + score partials (bit-identical to R7 scores)
    {
        dim3 grid(NTILES, NMTILE);
        gemm_fused_kernel<<<grid, 256, SMEM_BYTES>>>(span_emb, W1, b1, W2);
    }

    // 2) score reduce
    reduce_scores_kernel<<<(M_CAND + 255) / 256, 256>>>(b2);

    // 3) sort
    build_keys_kernel<<<SORT_N / 256, 256>>>();
    bitonic_local_sort<<<16, 1024>>>();
    for (int k = 8192; k <= SORT_N; k <<= 1) {
        for (int j = k >> 1; j >= 4096; j >>= 1)
            bitonic_global_step<<<SORT_N / 256, 256>>>(k, j);
        bitonic_local_merge<<<16, 1024>>>(k);
    }

    // 4) extraction
    extract_kernel<<<1, 1024>>>(starts, ends, ntop);

    // 5) gather
    const long long full_sz = (long long)2 * NTOP + (long long)NTOP * K_DIM;
    int full_layout = (out_size == (int)full_sz) ? 1 : (out_size == NTOP * K_DIM ? 0 : 1);
    gather_kernel<<<NTOP, 256>>>(span_emb, (float*)d_out, full_layout);
}

// round 17
// speedup vs baseline: 1.2145x; 1.2145x over previous
#include <cuda_runtime.h>
#include <cstdint>

// Problem constants (fixed by reference)
#define M_CAND    50000
#define K_DIM     2304
#define N_HID     1000
#define NUM_WORDS 5000
#define NTOP      2000
#define MAXW      10
#define SORT_N    65536
#define NTILES    8        // ceil(N_HID/128)

// GEMM tiling: 128x128 tile, k-chunk 8 (R7 layout), cp.async double-buffered
#define KC        8
#define NCHUNK    (K_DIM / KC)              // 288
#define NMTILE    ((M_CAND + 127) / 128)    // 391
#define STAGE_F   (KC * 128 * 2)            // As[8][128] + Bs[8][128] = 2048 floats
#define SMEM_BYTES (2 * STAGE_F * 4)        // 16384

// -------- scratch (device globals; no allocation allowed) --------
__device__ float               g_partial[(size_t)M_CAND * NTILES];
__device__ float               g_scores[M_CAND];
__device__ unsigned long long  g_keys[SORT_N];
__device__ int                 g_sel[NTOP];

// ---- packed f32x2 helpers (IEEE-exact: lanes are independent fp32 FMAs) ----
__device__ __forceinline__ unsigned long long pk2(float x, float y) {
    unsigned long long r;
    asm("mov.b64 %0, {%1, %2};" : "=l"(r) : "f"(x), "f"(y));
    return r;
}
__device__ __forceinline__ void upk2(unsigned long long v, float& x, float& y) {
    asm("mov.b64 {%0, %1}, %2;" : "=f"(x), "=f"(y) : "l"(v));
}
__device__ __forceinline__ unsigned long long ffma2(unsigned long long a,
                                                    unsigned long long b,
                                                    unsigned long long c) {
    unsigned long long d;
    asm("fma.rn.f32x2 %0, %1, %2, %3;" : "=l"(d) : "l"(a), "l"(b), "l"(c));
    return d;
}

// ---- cp.async helpers (sm_80+ base ISA; zero register staging, zero-fill tail) ----
__device__ __forceinline__ void cp_async16(uint32_t saddr, const void* gptr, int src_bytes) {
    asm volatile("cp.async.cg.shared.global [%0], [%1], 16, %2;\n"
                 :: "r"(saddr), "l"(gptr), "r"(src_bytes));
}
__device__ __forceinline__ void cp_commit() {
    asm volatile("cp.async.commit_group;\n" ::: "memory");
}
__device__ __forceinline__ void cp_wait0() {
    asm volatile("cp.async.wait_group 0;\n" ::: "memory");
}

// ============================================================
// 1) Fused GEMM: h = relu(A@W1 + b1); partial = h_tile . W2_tile
//    Inner loop + smem contents byte-identical to the R7 passing kernel
//    (scores bit-identical; rel_err locked at 9.569133e-07).
//    New: cp.async for B (no reg staging) + 1-chunk A reg prefetch (4 regs),
//    double-buffered, one __syncthreads per chunk.
// ============================================================
__global__ void __launch_bounds__(256, 2)
gemm_fused_kernel(const float* __restrict__ A,
                  const float* __restrict__ B,
                  const float* __restrict__ b1,
                  const float* __restrict__ W2) {
    extern __shared__ float sm[];
    // per-stage layout: As = stage[0..1023] as [k][row], Bs = stage[1024..2047] as [k][col]

    const int bm = blockIdx.y * 128;
    const int bn = blockIdx.x * 128;
    const int tid = threadIdx.x;
    const int tm = tid >> 4, tn = tid & 15;

    // A loader (R7): one float4: row a_row, cols a_col..a_col+3 -> transposed store
    const int a_row = tid >> 1, a_col = (tid & 1) << 2;
    const int gr = bm + a_row;
    // B loader (R7): one float4: k-row b_row, cols b_col..b_col+3 -> direct 16B
    const int b_row = tid >> 5, b_col = (tid & 31) << 2;
    const int gc = bn + b_col;
    int bsz = (N_HID - gc) * 4;
    bsz = bsz < 0 ? 0 : (bsz > 16 ? 16 : bsz);
    const int gc_safe = gc < N_HID ? gc : 0;   // valid addr even when bsz==0

    const uint32_t smem_u32 = (uint32_t)__cvta_generic_to_shared(sm);

    unsigned long long acc2[8][4];
#pragma unroll
    for (int i = 0; i < 8; i++)
#pragma unroll
        for (int jp = 0; jp < 4; jp++) acc2[i][jp] = 0ull;

    // ---- chunk load helpers ----
    auto issue_b = [&](int c, int buf) {
        const int k0 = c * KC;
        uint32_t dst = smem_u32 + (buf * STAGE_F + 1024 + b_row * 128 + b_col) * 4;
        cp_async16(dst, &B[(size_t)(k0 + b_row) * N_HID + gc_safe], bsz);
        cp_commit();
    };
    auto load_a = [&](int c) -> float4 {
        float4 v = make_float4(0.f, 0.f, 0.f, 0.f);
        if (gr < M_CAND)
            v = *reinterpret_cast<const float4*>(&A[(size_t)gr * K_DIM + c * KC + a_col]);
        return v;
    };
    auto store_a = [&](float4 v, int buf) {
        float* As = sm + buf * STAGE_F;
        As[(a_col + 0) * 128 + a_row] = v.x;
        As[(a_col + 1) * 128 + a_row] = v.y;
        As[(a_col + 2) * 128 + a_row] = v.z;
        As[(a_col + 3) * 128 + a_row] = v.w;
    };

    // prologue: stage chunk 0 into buffer 0
    issue_b(0, 0);
    store_a(load_a(0), 0);
    cp_wait0();
    __syncthreads();

    for (int c = 0; c < NCHUNK; c++) {
        const int buf = c & 1;
        float4 avA;
        if (c + 1 < NCHUNK) {
            issue_b(c + 1, buf ^ 1);
            avA = load_a(c + 1);       // LDG in flight across compute
        }

        const float* As = sm + buf * STAGE_F;
        const float* Bs = As + 1024;
#pragma unroll
        for (int k = 0; k < KC; k++) {
            float4 ra0 = *reinterpret_cast<const float4*>(&As[k * 128 + tm * 8]);
            float4 ra1 = *reinterpret_cast<const float4*>(&As[k * 128 + tm * 8 + 4]);
            const ulonglong2* bp =
                reinterpret_cast<const ulonglong2*>(&Bs[k * 128 + tn * 8]);
            ulonglong2 bA = bp[0], bB = bp[1];
            unsigned long long rb2[4] = {bA.x, bA.y, bB.x, bB.y};
            float ra[8] = {ra0.x, ra0.y, ra0.z, ra0.w, ra1.x, ra1.y, ra1.z, ra1.w};
#pragma unroll
            for (int i = 0; i < 8; i++) {
                unsigned long long aspl = pk2(ra[i], ra[i]);
#pragma unroll
                for (int jp = 0; jp < 4; jp++)
                    acc2[i][jp] = ffma2(aspl, rb2[jp], acc2[i][jp]);
            }
        }

        if (c + 1 < NCHUNK) {
            store_a(avA, buf ^ 1);
            cp_wait0();                // B(c+1) landed (issued one full compute ago)
        }
        __syncthreads();
    }

    // Fused epilogue: relu(acc + b1) dot W2 per row — identical order to R7
    float rowsum[8];
#pragma unroll
    for (int i = 0; i < 8; i++) rowsum[i] = 0.f;
#pragma unroll
    for (int jp = 0; jp < 4; jp++) {
#pragma unroll
        for (int h = 0; h < 2; h++) {
            int j = 2 * jp + h;
            int col = bn + tn * 8 + j;
            if (col < N_HID) {
                float w = W2[col];
                float bb = b1[col];
#pragma unroll
                for (int i = 0; i < 8; i++) {
                    float v0, v1;
                    upk2(acc2[i][jp], v0, v1);
                    float v = (h == 0 ? v0 : v1) + bb;
                    v = v > 0.f ? v : 0.f;
                    rowsum[i] = fmaf(v, w, rowsum[i]);
                }
            }
        }
    }
    // reuse smem as sred[128][17] (all compute in regs; last loop iter ended in sync)
    float* sred = sm;
#pragma unroll
    for (int i = 0; i < 8; i++) sred[(tm * 8 + i) * 17 + tn] = rowsum[i];
    __syncthreads();

    if (tid < 128) {
        float s = 0.f;
#pragma unroll
        for (int t = 0; t < 16; t++) s += sred[tid * 17 + t];   // tn ascending
        int r = bm + tid;
        if (r < M_CAND) g_partial[(size_t)r * NTILES + blockIdx.x] = s;
    }
}

// ============================================================
// 2) scores[i] = sum_t partial[i][t] + b2  (fixed order)
// ============================================================
__global__ void reduce_scores_kernel(const float* __restrict__ b2) {
    int i = blockIdx.x * blockDim.x + threadIdx.x;
    if (i < M_CAND) {
        float s = 0.f;
#pragma unroll
        for (int t = 0; t < NTILES; t++) s += g_partial[(size_t)i * NTILES + t];
        g_scores[i] = s + b2[0];
    }
}

// ============================================================
// 3) sort keys: (descending score bits << 32) | idx -> ascending u64 sort
// ============================================================
__global__ void build_keys_kernel() {
    int i = blockIdx.x * blockDim.x + threadIdx.x;
    if (i >= SORT_N) return;
    if (i < M_CAND) {
        unsigned u = __float_as_uint(g_scores[i]);
        unsigned m = (u & 0x80000000u) ? ~u : (u | 0x80000000u);
        unsigned d = ~m;
        g_keys[i] = (((unsigned long long)d) << 32) | (unsigned)i;
    } else {
        g_keys[i] = ~0ull;
    }
}

__device__ __forceinline__ void cmpswap(unsigned long long& a, unsigned long long& b, bool up) {
    if ((a > b) == up) { unsigned long long t = a; a = b; b = t; }
}

__global__ void bitonic_local_sort() {
    __shared__ unsigned long long s[4096];
    const int base = blockIdx.x * 4096;
    for (int i = threadIdx.x; i < 4096; i += blockDim.x) s[i] = g_keys[base + i];
    __syncthreads();
    for (int k = 2; k <= 4096; k <<= 1) {
        for (int j = k >> 1; j > 0; j >>= 1) {
            for (int i = threadIdx.x; i < 4096; i += blockDim.x) {
                int l = i ^ j;
                if (l > i) {
                    bool up = (((base + i) & k) == 0);
                    unsigned long long a = s[i], b = s[l];
                    cmpswap(a, b, up);
                    s[i] = a; s[l] = b;
                }
            }
            __syncthreads();
        }
    }
    for (int i = threadIdx.x; i < 4096; i += blockDim.x) g_keys[base + i] = s[i];
}

__global__ void bitonic_global_step(int k, int j) {
    int i = blockIdx.x * blockDim.x + threadIdx.x;
    if (i >= SORT_N) return;
    int l = i ^ j;
    if (l > i) {
        unsigned long long a = g_keys[i], b = g_keys[l];
        bool up = ((i & k) == 0);
        if ((a > b) == up) { g_keys[i] = b; g_keys[l] = a; }
    }
}

__global__ void bitonic_local_merge(int k) {
    __shared__ unsigned long long s[4096];
    const int base = blockIdx.x * 4096;
    for (int i = threadIdx.x; i < 4096; i += blockDim.x) s[i] = g_keys[base + i];
    __syncthreads();
    for (int j = 2048; j > 0; j >>= 1) {
        for (int i = threadIdx.x; i < 4096; i += blockDim.x) {
            int l = i ^ j;
            if (l > i) {
                bool up = (((base + i) & k) == 0);
                unsigned long long a = s[i], b = s[l];
                cmpswap(a, b, up);
                s[i] = a; s[l] = b;
            }
        }
        __syncthreads();
    }
    for (int i = threadIdx.x; i < 4096; i += blockDim.x) g_keys[base + i] = s[i];
}

// ============================================================
// 4) greedy extraction: batched shared prefetch + warp-serial scan
// ============================================================
#define XB 1024

__global__ void extract_kernel(const int* __restrict__ starts,
                               const int* __restrict__ ends,
                               const int* __restrict__ ntop_ptr) {
    __shared__ short stme[NUM_WORDS];
    __shared__ short etms[NUM_WORDS];
    __shared__ unsigned long long acc[2048];
    __shared__ int   sh_count;
    __shared__ int   sh_done;
    __shared__ int   bc[XB];
    __shared__ short bs[XB], be[XB];
    const int tid = threadIdx.x;

    for (int i = tid; i < NUM_WORDS; i += blockDim.x) { stme[i] = -1; etms[i] = -1; }
    for (int i = tid; i < 2048; i += blockDim.x) acc[i] = ~0ull;
    if (tid == 0) sh_done = 0;
    __syncthreads();

    int ntop = NTOP;
    if (ntop_ptr) { int v = *ntop_ptr; ntop = v < NTOP ? v : NTOP; }
    int count = 0;

    for (int base = 0; base < M_CAND; base += XB) {
        if (sh_done) break;
        int i = base + tid;
        if (i < M_CAND) {
            unsigned long long kv = g_keys[i];
            int cand = (int)(unsigned)(kv & 0xFFFFFFFFull);
            bc[tid] = cand;
            bs[tid] = (short)starts[cand];
            be[tid] = (short)ends[cand];
        }
        __syncthreads();

        if (tid < 32) {
            const int lane = tid;
            int n = M_CAND - base; if (n > XB) n = XB;
            for (int t = 0; t < n && count < ntop; t++) {
                int s = (int)bs[t], e = (int)be[t];
                bool c = false;
                if (lane <= MAXW) {
                    int pos = s + lane;
                    if (pos <= e) {
                        int me = (int)stme[pos];
                        int ms = (int)etms[pos];
                        c = ((pos > s) && (me > e)) || ((pos < e) && (ms >= 0) && (ms < s));
                    }
                }
                unsigned b = __ballot_sync(0xffffffffu, c);
                if (b == 0u) {
                    if (lane == 0) {
                        if (e > (int)stme[s]) stme[s] = (short)e;
                        int tt = (int)etms[e];
                        if (tt == -1 || s < tt) etms[e] = (short)s;
                        acc[count] = (((unsigned long long)(s * NUM_WORDS + e)) << 27)
                                   | (((unsigned long long)count) << 16)
                                   | (unsigned long long)(unsigned)bc[t];
                    }
                    count++;
                }
                __syncwarp();
            }
            if (lane == 0 && count >= ntop) sh_done = 1;
        }
        __syncthreads();
    }

    if (tid == 0) sh_count = count;
    __syncthreads();

    for (int k = 2; k <= 2048; k <<= 1) {
        for (int j = k >> 1; j > 0; j >>= 1) {
            for (int i = tid; i < 2048; i += blockDim.x) {
                int l = i ^ j;
                if (l > i) {
                    bool up = ((i & k) == 0);
                    unsigned long long a = acc[i], b = acc[l];
                    cmpswap(a, b, up);
                    acc[i] = a; acc[l] = b;
                }
            }
            __syncthreads();
        }
    }
    const int cnt = sh_count;
    for (int i = tid; i < NTOP; i += blockDim.x) {
        unsigned long long v = (i < cnt) ? acc[i] : acc[0];
        g_sel[i] = (int)(v & 0xFFFFull);
    }
}

// ============================================================
// 5) gather outputs: [idx(float) | scores | emb rows]
// ============================================================
__global__ void gather_kernel(const float* __restrict__ emb, float* __restrict__ out,
                              int full_layout) {
    const int b = blockIdx.x;
    const int sel = g_sel[b];
    float* oemb = out + (full_layout ? 2 * NTOP : 0);
    if (full_layout && threadIdx.x == 0) {
        out[b]        = (float)sel;
        out[NTOP + b] = g_scores[sel];
    }
    const float4* src = reinterpret_cast<const float4*>(&emb[(size_t)sel * K_DIM]);
    float4* dst       = reinterpret_cast<float4*>(&oemb[(size_t)b * K_DIM]);
    for (int j = threadIdx.x; j < K_DIM / 4; j += blockDim.x) dst[j] = src[j];
}

// ============================================================
extern "C" void kernel_launch(void* const* d_in, const int* in_sizes, int n_in,
                              void* d_out, int out_size) {
    const float* span_emb = (const float*)d_in[0];
    const float* W1       = (const float*)d_in[1];
    const float* b1       = (const float*)d_in[2];
    const float* W2       = (const float*)d_in[3];
    const float* b2       = (const float*)d_in[4];
    const int*   starts   = (const int*)d_in[5];
    const int*   ends     = (const int*)d_in[6];
    const int*   ntop     = (n_in > 7) ? (const int*)d_in[7] : nullptr;

    // 1) fused GEMM + bias + relu + score partials (bit-identical to R7 scores)
    {
        dim3 grid(NTILES, NMTILE);
        gemm_fused_kernel<<<grid, 256, SMEM_BYTES>>>(span_emb, W1, b1, W2);
    }

    // 2) score reduce
    reduce_scores_kernel<<<(M_CAND + 255) / 256, 256>>>(b2);

    // 3) sort
    build_keys_kernel<<<SORT_N / 256, 256>>>();
    bitonic_local_sort<<<16, 1024>>>();
    for (int k = 8192; k <= SORT_N; k <<= 1) {
        for (int j = k >> 1; j >= 4096; j >>= 1)
            bitonic_global_step<<<SORT_N / 256, 256>>>(k, j);
        bitonic_local_merge<<<16, 1024>>>(k);
    }

    // 4) extraction
    extract_kernel<<<1, 1024>>>(starts, ends, ntop);

    // 5) gather
    const long long full_sz = (long long)2 * NTOP + (long long)NTOP * K_DIM;
    int full_layout = (out_size == (int)full_sz) ? 1 : (out_size == NTOP * K_DIM ? 0 : 1);
    gather_kernel<<<NTOP, 256>>>(span_emb, (float*)d_out, full_layout);
}